// round 17
// baseline (speedup 1.0000x reference)
#include <cuda_runtime.h>
#include <cuda_fp16.h>
#include <cstdint>

// Problem constants
#define NB    32
#define CLOC  512
#define HW2   196
#define NHW   6272
#define DGLB  2048
#define HIDN  256
#define EPSC  1e-10f
#define NJT   49                    // j-tiles of 128
#define NTILE (NJT * NB)            // 1568 tiles
#define NCTA  148                   // persistent CTAs (== grid, all resident)

// Scratch (device globals; no allocation allowed)
__device__ float    g_hloc[NHW * HIDN];      // 6.4 MB
__device__ float    g_hglb[NB * HIDN];
__device__ float    g_scores[NB * NHW];      // 0.8 MB
__device__ uint2    g_W2f[16 * 4 * 8 * 32];  // 128 KB, fragment order
__device__ unsigned long long g_bar;         // monotone grid-barrier ticket

// ---------------------------------------------------------------------------
// helpers
// ---------------------------------------------------------------------------
__device__ __forceinline__ void mma16(float* c, const uint32_t* a,
                                      uint32_t b0, uint32_t b1) {
    asm volatile(
        "mma.sync.aligned.m16n8k16.row.col.f32.f16.f16.f32 "
        "{%0,%1,%2,%3}, {%4,%5,%6,%7}, {%8,%9}, {%0,%1,%2,%3};"
        : "+f"(c[0]), "+f"(c[1]), "+f"(c[2]), "+f"(c[3])
        : "r"(a[0]), "r"(a[1]), "r"(a[2]), "r"(a[3]), "r"(b0), "r"(b1));
}
__device__ __forceinline__ uint32_t smem_u32(const void* p) {
    uint32_t a;
    asm("{ .reg .u64 t; cvta.to.shared.u64 t, %1; cvt.u32.u64 %0, t; }" : "=r"(a) : "l"(p));
    return a;
}
__device__ __forceinline__ void cpa16(uint32_t dst, const void* src) {
    asm volatile("cp.async.ca.shared.global [%0], [%1], 16;" :: "r"(dst), "l"(src));
}
#define CPA_COMMIT() asm volatile("cp.async.commit_group;" ::: "memory")

// Grid barrier: all NCTA CTAs resident -> spin is safe. Monotone ticket
// counter survives CUDA-graph replays (no reset needed).
__device__ __forceinline__ void grid_bar() {
    __syncthreads();
    if (threadIdx.x == 0) {
        __threadfence();
        unsigned long long t = atomicAdd(&g_bar, 1ULL);
        unsigned long long tgt = (t / NCTA + 1ULL) * NCTA;
        while (*(volatile unsigned long long*)&g_bar < tgt) { __nanosleep(64); }
    }
    __syncthreads();
    __threadfence();
}

// ---------------------------------------------------------------------------
// smem layout (single 172 KB arena, phases reuse it)
// phase0 hloc: A 2x5120 @0, B 2x16896 @10240  (total 44032)
// score: AS 2x18432 @0, BS 131072 @36864, b2/w3/red tail
// ---------------------------------------------------------------------------
#define HLA_B    5120                               // 64 rows x 40 halves
#define HLB_B    16896                              // 16 k2 x 264 words
#define AS_STRH  72
#define AS_BYTES (128 * AS_STRH * 2)                // 18432
#define BCHUNK   32768
#define AS_OFF   0
#define BS_OFF   (2 * AS_BYTES)                     // 36864
#define B2_OFF   (BS_OFF + 4 * BCHUNK)              // 167936
#define W3_OFF   (B2_OFF + 1024)
#define RED_OFF  (W3_OFF + 1024)
#define SM_TOTAL (RED_OFF + 128 * 4 * 4)            // 172032

__global__ __launch_bounds__(512, 1) void fused_kernel(
    const float* __restrict__ LF, const float* __restrict__ gf,
    const float* __restrict__ W1, const float* __restrict__ b1,
    const float* __restrict__ W2, const float* __restrict__ b2,
    const float* __restrict__ W3, const float* __restrict__ b3p,
    float* __restrict__ out) {
    extern __shared__ char smem[];
    const uint32_t sbase = smem_u32(smem);
    const int tid = threadIdx.x;
    const int bid = blockIdx.x;
    const int wid = tid >> 5, lid = tid & 31;
    const int g   = lid >> 2, tig = lid & 3;

    // ======================= PHASE 0 =======================
    if (bid < 98) {
        // ---- hloc: 64-row tile, fp16 mma, 16 warps = 2m x 8n ----
        const float* W1loc = W1 + (size_t)DGLB * HIDN;
        const int m0w = (wid & 1) * 32;
        const int n0w = (wid >> 1) * 32;
        const int j0  = bid * 64;
        const int arow = tid & 63, akq = tid >> 6;        // A: 4 halves each
        const int j   = j0 + arow;
        const int n_  = j / HW2, pos = j % HW2;
        const size_t abase = (size_t)n_ * CLOC * HW2 + pos;
        const int bn4 = tid & 63, bkb = tid >> 6;         // B: 2 k2-rows each

        float acc[2][4][4];
        #pragma unroll
        for (int mt = 0; mt < 2; mt++)
            #pragma unroll
            for (int nt = 0; nt < 4; nt++)
                #pragma unroll
                for (int q = 0; q < 4; q++) acc[mt][nt][q] = 0.f;

        {   // build chunk 0
            __half* A0 = (__half*)smem;
            uint32_t* B0 = (uint32_t*)(smem + 2 * HLA_B);
            float f0 = LF[abase + (size_t)(akq * 4 + 0) * HW2];
            float f1 = LF[abase + (size_t)(akq * 4 + 1) * HW2];
            float f2 = LF[abase + (size_t)(akq * 4 + 2) * HW2];
            float f3 = LF[abase + (size_t)(akq * 4 + 3) * HW2];
            __half2 h01 = __floats2half2_rn(f0, f1);
            __half2 h23 = __floats2half2_rn(f2, f3);
            *(uint2*)(A0 + arow * 40 + akq * 4) =
                make_uint2(*(uint32_t*)&h01, *(uint32_t*)&h23);
            #pragma unroll
            for (int r = 0; r < 2; r++) {
                int k2 = bkb + r * 8;
                float4 va = *(const float4*)&W1loc[(size_t)(2 * k2)     * HIDN + bn4 * 4];
                float4 vb = *(const float4*)&W1loc[(size_t)(2 * k2 + 1) * HIDN + bn4 * 4];
                __half2 p0 = __floats2half2_rn(va.x, vb.x);
                __half2 p1 = __floats2half2_rn(va.y, vb.y);
                __half2 p2 = __floats2half2_rn(va.z, vb.z);
                __half2 p3 = __floats2half2_rn(va.w, vb.w);
                uint32_t* d = B0 + k2 * 264 + bn4 * 4;
                d[0] = *(uint32_t*)&p0; d[1] = *(uint32_t*)&p1;
                d[2] = *(uint32_t*)&p2; d[3] = *(uint32_t*)&p3;
            }
        }
        __syncthreads();

        for (int c = 0; c < 16; c++) {
            const int pb = c & 1, nb = pb ^ 1;
            const uint32_t* AsU = (const uint32_t*)(smem + pb * HLA_B);
            const uint32_t* BsU = (const uint32_t*)(smem + 2 * HLA_B + pb * HLB_B);

            float aR[4];
            float4 bRa[2], bRb[2];
            if (c < 15) {
                const int kb = (c + 1) * 32;
                #pragma unroll
                for (int q = 0; q < 4; q++)
                    aR[q] = LF[abase + (size_t)(kb + akq * 4 + q) * HW2];
                #pragma unroll
                for (int r = 0; r < 2; r++) {
                    int gk = kb + 2 * (bkb + r * 8);
                    bRa[r] = *(const float4*)&W1loc[(size_t)gk       * HIDN + bn4 * 4];
                    bRb[r] = *(const float4*)&W1loc[(size_t)(gk + 1) * HIDN + bn4 * 4];
                }
            }

            #pragma unroll
            for (int s = 0; s < 2; s++) {
                const int kw = s * 8;
                uint32_t a[2][4];
                #pragma unroll
                for (int mt = 0; mt < 2; mt++) {
                    int mr = m0w + mt * 16 + g;
                    a[mt][0] = AsU[mr * 20 + kw + tig];
                    a[mt][1] = AsU[(mr + 8) * 20 + kw + tig];
                    a[mt][2] = AsU[mr * 20 + kw + tig + 4];
                    a[mt][3] = AsU[(mr + 8) * 20 + kw + tig + 4];
                }
                #pragma unroll
                for (int nt = 0; nt < 4; nt++) {
                    int nc = n0w + nt * 8 + g;
                    uint32_t b0 = BsU[(s * 8 + tig) * 264 + nc];
                    uint32_t b1_ = BsU[(s * 8 + tig + 4) * 264 + nc];
                    mma16(acc[0][nt], a[0], b0, b1_);
                    mma16(acc[1][nt], a[1], b0, b1_);
                }
            }

            if (c < 15) {
                __half* AN = (__half*)(smem + nb * HLA_B);
                uint32_t* BN = (uint32_t*)(smem + 2 * HLA_B + nb * HLB_B);
                __half2 h01 = __floats2half2_rn(aR[0], aR[1]);
                __half2 h23 = __floats2half2_rn(aR[2], aR[3]);
                *(uint2*)(AN + arow * 40 + akq * 4) =
                    make_uint2(*(uint32_t*)&h01, *(uint32_t*)&h23);
                #pragma unroll
                for (int r = 0; r < 2; r++) {
                    int k2 = bkb + r * 8;
                    __half2 p0 = __floats2half2_rn(bRa[r].x, bRb[r].x);
                    __half2 p1 = __floats2half2_rn(bRa[r].y, bRb[r].y);
                    __half2 p2 = __floats2half2_rn(bRa[r].z, bRb[r].z);
                    __half2 p3 = __floats2half2_rn(bRa[r].w, bRb[r].w);
                    uint32_t* d = BN + k2 * 264 + bn4 * 4;
                    d[0] = *(uint32_t*)&p0; d[1] = *(uint32_t*)&p1;
                    d[2] = *(uint32_t*)&p2; d[3] = *(uint32_t*)&p3;
                }
            }
            __syncthreads();
        }

        #pragma unroll
        for (int mt = 0; mt < 2; mt++) {
            int row0 = j0 + m0w + mt * 16 + g;
            #pragma unroll
            for (int nt = 0; nt < 4; nt++) {
                int ncol = n0w + nt * 8 + 2 * tig;
                *(float2*)&g_hloc[(size_t)row0 * HIDN + ncol] =
                    make_float2(acc[mt][nt][0], acc[mt][nt][1]);
                *(float2*)&g_hloc[(size_t)(row0 + 8) * HIDN + ncol] =
                    make_float2(acc[mt][nt][2], acc[mt][nt][3]);
            }
        }
    } else if (bid < 130) {
        // ---- hglb: one CTA per i, 2-way K-split ----
        float* red = (float*)smem;
        const int i  = bid - 98;
        const int o  = tid & 255;
        const int kq = tid >> 8;                 // 0..1
        const float* gp = gf + i * DGLB + kq * 1024;
        const float* wp = W1 + (size_t)(kq * 1024) * HIDN + o;
        float s0 = 0.f, s1 = 0.f;
        #pragma unroll 8
        for (int k = 0; k < 1024; k += 2) {
            s0 += gp[k]     * wp[(size_t)k * HIDN];
            s1 += gp[k + 1] * wp[(size_t)(k + 1) * HIDN];
        }
        red[tid] = s0 + s1;
        __syncthreads();
        if (tid < 256)
            g_hglb[i * HIDN + tid] = red[tid] + red[tid + 256] + b1[tid];
    } else if (bid < 138) {
        // ---- W2 fragment pack ----
        const int pid0 = ((bid - 130) * 512 + tid) * 4;
        #pragma unroll
        for (int q = 0; q < 4; q++) {
            int id   = pid0 + q;
            int lane = id & 31;
            int nt   = (id >> 5) & 7;
            int nwp  = (id >> 8) & 3;
            int ks   = id >> 10;
            int gq   = lane >> 2, tg = lane & 3;
            int n    = nwp * 64 + nt * 8 + gq;
            int k0   = ks * 16 + 2 * tg;
            __half2 w0 = __floats2half2_rn(W2[(size_t)k0 * HIDN + n],
                                           W2[(size_t)(k0 + 1) * HIDN + n]);
            __half2 w1 = __floats2half2_rn(W2[(size_t)(k0 + 8) * HIDN + n],
                                           W2[(size_t)(k0 + 9) * HIDN + n]);
            g_W2f[id] = make_uint2(*(uint32_t*)&w0, *(uint32_t*)&w1);
        }
    }

    grid_bar();   // ======== phase 0 complete ========

    // ======================= SCORE PHASE (all CTAs) =======================
    {
        float* b2s = (float*)(smem + B2_OFF);
        float* w3s = (float*)(smem + W3_OFF);
        float* red = (float*)(smem + RED_OFF);
        const int m0w = (wid & 3) * 32;
        const int nw  = wid >> 2;
        const int n0w = nw * 64;

        {
            const char* bsrc = (const char*)g_W2f;
            #pragma unroll
            for (int cg2 = 0; cg2 < 4; cg2++) {
                #pragma unroll
                for (int r = 0; r < 4; r++) {
                    int off = cg2 * BCHUNK + (tid + r * 512) * 16;
                    cpa16(sbase + BS_OFF + off, bsrc + off);
                }
                CPA_COMMIT();
            }
        }

        if (tid < 256) { b2s[tid] = b2[tid]; w3s[tid] = W3[tid]; }
        const float b3v = b3p[0];

        const int k4   = tid & 15;
        const int mrow = tid >> 4;

        float acc[2][8][4];
        #pragma unroll
        for (int mt = 0; mt < 2; mt++)
            #pragma unroll
            for (int nt = 0; nt < 8; nt++)
                #pragma unroll
                for (int q = 0; q < 4; q++) acc[mt][nt][q] = 0.f;

        {
            const int t0 = bid;
            const float* hl = g_hloc + (size_t)(t0 % NJT) * 128 * HIDN;
            const float* gb = g_hglb + (t0 / NJT) * HIDN;
            float4 gv = *(const float4*)(gb + k4 * 4);
            __half* As0 = (__half*)(smem + AS_OFF);
            #pragma unroll
            for (int r = 0; r < 4; r++) {
                int m = mrow + r * 32;
                float4 v = *(const float4*)(hl + (size_t)m * HIDN + k4 * 4);
                __half2 h01 = __floats2half2_rn(fmaxf(v.x + gv.x, 0.f), fmaxf(v.y + gv.y, 0.f));
                __half2 h23 = __floats2half2_rn(fmaxf(v.z + gv.z, 0.f), fmaxf(v.w + gv.w, 0.f));
                *(uint2*)(As0 + m * AS_STRH + k4 * 4) =
                    make_uint2(*(uint32_t*)&h01, *(uint32_t*)&h23);
            }
            asm volatile("cp.async.wait_group 3;" ::: "memory");
            __syncthreads();
        }

        const uint2* BsP = (const uint2*)(smem + BS_OFF);
        int cg = 0;

        for (int t = bid; t < NTILE; t += NCTA) {
            const int jt = t % NJT, ii = t / NJT;

            for (int c = 0; c < 4; c++) {
                const int pb = cg & 1, nb = pb ^ 1;
                const uint32_t* AsU = (const uint32_t*)(smem + AS_OFF + pb * AS_BYTES);

                const bool hn = (c < 3) || (t + NCTA < NTILE);
                float4 areg[4];
                float4 gvn;
                if (hn) {
                    const int t2 = (c < 3) ? t : t + NCTA;
                    const int c2 = (c < 3) ? c + 1 : 0;
                    const float* hl2 = g_hloc + (size_t)(t2 % NJT) * 128 * HIDN;
                    const float* gb2 = g_hglb + (t2 / NJT) * HIDN;
                    const int kb2 = c2 * 64;
                    gvn = *(const float4*)(gb2 + kb2 + k4 * 4);
                    #pragma unroll
                    for (int r = 0; r < 4; r++) {
                        int m = mrow + r * 32;
                        areg[r] = *(const float4*)(hl2 + (size_t)m * HIDN + kb2 + k4 * 4);
                    }
                }

                #pragma unroll
                for (int kk = 0; kk < 4; kk++) {
                    const int kw = kk * 8;
                    const int ks = c * 4 + kk;
                    uint32_t a[2][4];
                    #pragma unroll
                    for (int mt = 0; mt < 2; mt++) {
                        int mr = m0w + mt * 16 + g;
                        a[mt][0] = AsU[mr * 36 + kw + tig];
                        a[mt][1] = AsU[(mr + 8) * 36 + kw + tig];
                        a[mt][2] = AsU[mr * 36 + kw + tig + 4];
                        a[mt][3] = AsU[(mr + 8) * 36 + kw + tig + 4];
                    }
                    #pragma unroll
                    for (int nt = 0; nt < 8; nt++) {
                        uint2 bw = BsP[((ks * 4 + nw) * 8 + nt) * 32 + lid];
                        mma16(acc[0][nt], a[0], bw.x, bw.y);
                        mma16(acc[1][nt], a[1], bw.x, bw.y);
                    }
                }

                if (hn) {
                    __half* AsN = (__half*)(smem + AS_OFF + nb * AS_BYTES);
                    #pragma unroll
                    for (int r = 0; r < 4; r++) {
                        int m = mrow + r * 32;
                        __half2 h01 = __floats2half2_rn(fmaxf(areg[r].x + gvn.x, 0.f),
                                                        fmaxf(areg[r].y + gvn.y, 0.f));
                        __half2 h23 = __floats2half2_rn(fmaxf(areg[r].z + gvn.z, 0.f),
                                                        fmaxf(areg[r].w + gvn.w, 0.f));
                        *(uint2*)(AsN + m * AS_STRH + k4 * 4) =
                            make_uint2(*(uint32_t*)&h01, *(uint32_t*)&h23);
                    }
                }
                if (cg == 0)      asm volatile("cp.async.wait_group 2;" ::: "memory");
                else if (cg == 1) asm volatile("cp.async.wait_group 1;" ::: "memory");
                else if (cg == 2) asm volatile("cp.async.wait_group 0;" ::: "memory");
                __syncthreads();
                cg++;
            }

            #pragma unroll
            for (int mt = 0; mt < 2; mt++) {
                float s0 = 0.f, s1 = 0.f;
                #pragma unroll
                for (int nt = 0; nt < 8; nt++) {
                    int n = n0w + nt * 8 + 2 * tig;
                    float w0 = w3s[n], w1 = w3s[n + 1];
                    float c0 = b2s[n], c1 = b2s[n + 1];
                    s0 += fmaxf(acc[mt][nt][0] + c0, 0.f) * w0
                        + fmaxf(acc[mt][nt][1] + c1, 0.f) * w1;
                    s1 += fmaxf(acc[mt][nt][2] + c0, 0.f) * w0
                        + fmaxf(acc[mt][nt][3] + c1, 0.f) * w1;
                }
                s0 += __shfl_xor_sync(0xffffffffu, s0, 1);
                s0 += __shfl_xor_sync(0xffffffffu, s0, 2);
                s1 += __shfl_xor_sync(0xffffffffu, s1, 1);
                s1 += __shfl_xor_sync(0xffffffffu, s1, 2);
                if (tig == 0) {
                    red[(m0w + mt * 16 + g) * 4 + nw]     = s0;
                    red[(m0w + mt * 16 + g + 8) * 4 + nw] = s1;
                }
            }
            #pragma unroll
            for (int mt = 0; mt < 2; mt++)
                #pragma unroll
                for (int nt = 0; nt < 8; nt++)
                    #pragma unroll
                    for (int q = 0; q < 4; q++) acc[mt][nt][q] = 0.f;
            __syncthreads();
            if (tid < 128) {
                float s = red[tid * 4] + red[tid * 4 + 1] + red[tid * 4 + 2] + red[tid * 4 + 3];
                g_scores[ii * NHW + jt * 128 + tid] = s + b3v;
            }
            __syncthreads();
        }
    }

    grid_bar();   // ======== scores complete ========

    // ======================= FINALIZE (bid < 32) =======================
    if (bid < NB) {
        float* fred = (float*)smem;          // 16 + 16 + 2 floats
        const int i = bid;
        const float* row = g_scores + i * NHW;
        const int lane = lid;

        float v[13];
        const bool hasX = (tid < NHW - 12 * 512);    // tid < 128
        float mx = -1e30f;
        #pragma unroll
        for (int k = 0; k < 12; k++) {
            v[k] = row[tid + k * 512];
            mx = fmaxf(mx, v[k]);
        }
        if (hasX) { v[12] = row[tid + 12 * 512]; mx = fmaxf(mx, v[12]); }

        #pragma unroll
        for (int off = 16; off; off >>= 1)
            mx = fmaxf(mx, __shfl_xor_sync(0xffffffffu, mx, off));
        if (lane == 0) fred[wid] = mx;
        __syncthreads();
        if (wid == 0) {
            float m = (lane < 16) ? fred[lane] : -1e30f;
            #pragma unroll
            for (int off = 8; off; off >>= 1)
                m = fmaxf(m, __shfl_xor_sync(0xffffffffu, m, off));
            if (lane == 0) fred[32] = m;
        }
        __syncthreads();
        mx = fred[32];

        const int lo = i * HW2, hi = lo + HW2;
        float sum = 0.f;
        #pragma unroll
        for (int k = 0; k < 12; k++) {
            int jj = tid + k * 512;
            if (jj < lo || jj >= hi) sum += __expf(v[k] - mx);
        }
        if (hasX) {
            int jj = tid + 12 * 512;
            if (jj < lo || jj >= hi) sum += __expf(v[12] - mx);
        }
        #pragma unroll
        for (int off = 16; off; off >>= 1)
            sum += __shfl_xor_sync(0xffffffffu, sum, off);
        __syncthreads();
        if (lane == 0) fred[wid] = sum;
        __syncthreads();
        if (wid == 0) {
            float s = (lane < 16) ? fred[lane] : 0.f;
            #pragma unroll
            for (int off = 8; off; off >>= 1)
                s += __shfl_xor_sync(0xffffffffu, s, off);
            if (lane == 0) fred[33] = s;
        }
        __syncthreads();

        const float neg_mean = fred[33] / (float)(NHW - HW2) + EPSC;
        const float lg = __logf(neg_mean);
        if (tid < HW2)
            out[i * HW2 + tid] = row[lo + tid] - mx - lg;
    }
}

// ---------------------------------------------------------------------------
extern "C" void kernel_launch(void* const* d_in, const int* in_sizes, int n_in,
                              void* d_out, int out_size) {
    const float* LF = (const float*)d_in[0];
    const float* GF = (const float*)d_in[1];
    const float* W1 = (const float*)d_in[2];
    const float* b1 = (const float*)d_in[3];
    const float* W2 = (const float*)d_in[4];
    const float* b2 = (const float*)d_in[5];
    const float* W3 = (const float*)d_in[6];
    const float* b3 = (const float*)d_in[7];
    float* out = (float*)d_out;

    cudaFuncSetAttribute(fused_kernel, cudaFuncAttributeMaxDynamicSharedMemorySize, SM_TOTAL);
    fused_kernel<<<NCTA, 512, SM_TOTAL>>>(LF, GF, W1, b1, W2, b2, W3, b3, out);
}